// round 6
// baseline (speedup 1.0000x reference)
#include <cuda_runtime.h>
#include <math.h>

#define BB 8
#define CC 128
#define HH 256
#define WW 256
#define NPIX (HH*WW)        // 65536
#define NPIX4 (NPIX/4)      // 16384
#define NOUT (BB*CC*NPIX)   // 67108864
#define OFF_ATTN ((size_t)NOUT)
#define OFF_W (OFF_ATTN + (size_t)BB*NPIX)
#define OFF_ALPHA (OFF_W + (size_t)BB*CC)
#define FNEG 3.402823466e38f

// db8 dec_lo (pywt), fp32
__constant__ float c_declo[16] = {
    -0.00011747678400228192f, 0.0006754494059985568f, -0.0003917403729959771f,
    -0.00487035299301066f, 0.008746094047015655f, 0.013981027917015516f,
    -0.04408825393106472f, -0.01736930100202211f, 0.128747426620186f,
    0.00047248457399797254f, -0.2840155429624281f, -0.015829105256023893f,
    0.5853546836548691f, 0.6756307362980128f, 0.3128715909144659f,
    0.05441584224308161f };

__device__ float g_wa[256];          // per-position separable DWT weight
__device__ float g_yraw[BB*CC];      // weighted sums (pre 1/135^2)
__device__ float g_wch[BB*CC];       // channel gate w
__device__ float g_alpha;
__device__ float g_s[BB*2*NPIX];     // [avg;max] maps, 4 MB scratch

__device__ __forceinline__ float warp_sum(float v) {
    v += __shfl_xor_sync(0xffffffffu, v, 16);
    v += __shfl_xor_sync(0xffffffffu, v, 8);
    v += __shfl_xor_sync(0xffffffffu, v, 4);
    v += __shfl_xor_sync(0xffffffffu, v, 2);
    v += __shfl_xor_sync(0xffffffffu, v, 1);
    return v;
}

// ---------------------------------------------------------------------------
// K0: zero accumulators, build a[256], alpha = sigmoid(weight).
// ---------------------------------------------------------------------------
__global__ void k0_init(const float* __restrict__ weight, float* __restrict__ d_out) {
    int t = threadIdx.x;                      // 288 threads
    if (t < 256) g_wa[t] = 0.f;
    for (int i = t; i < BB*CC; i += 288) g_yraw[i] = 0.f;
    if (t == 287) {
        float al = 1.f / (1.f + expf(-weight[0]));
        g_alpha = al;
        d_out[OFF_ALPHA] = al;
    }
    __syncthreads();
    if (t < 284) {
        int j = t + 1;                        // 1..284
        int m = (j < 15) ? (14 - j) : ((j <= 270) ? (j - 15) : (526 - j));
        int klo = j - 1 - 268; if (klo < 0) klo = 0;
        int khi = j - 1;       if (khi > 15) khi = 15;
        if ((klo & 1) != ((j - 1) & 1)) klo++;
        float add = 0.f;
        for (int k = klo; k <= khi; k += 2) add += c_declo[15 - k];
        if (add != 0.f) atomicAdd(&g_wa[m], add);
    }
}

// ---------------------------------------------------------------------------
// K1: stats pass. grid 4096 (= BB * 512 tiles), block 256 (8 warps).
// Block handles 32 float4-pixels x 128 channels (64 KB of x).
// Warp w owns channels c = w + 8j (j=0..15); lane owns one float4 pixel.
// avg/max in regs across 16 channel-iters, combined via 8 KB smem once.
// DWT sums: 16 reg accumulators/thread, one shuffle-reduce + atomic at end.
// ---------------------------------------------------------------------------
__global__ void __launch_bounds__(256) k1_reduce(const float* __restrict__ x) {
    __shared__ float4 ssum[8][32];
    __shared__ float4 smax[8][32];
    int t = threadIdx.x;
    int warp = t >> 5, lane = t & 31;
    int b = blockIdx.x >> 9;                  // batch
    int tile = blockIdx.x & 511;              // 512 tiles of 32 float4
    int g = tile * 32 + lane;                 // float4 index in plane

    float wh = g_wa[g >> 6];
    int w0 = (g & 63) << 2;
    float4 wt = make_float4(g_wa[w0]*wh, g_wa[w0+1]*wh,
                            g_wa[w0+2]*wh, g_wa[w0+3]*wh);

    const float4* xp = (const float4*)x + ((size_t)(b * CC) + warp) * NPIX4 + g;

    float4 psum = make_float4(0.f, 0.f, 0.f, 0.f);
    float4 pmax = make_float4(-FNEG, -FNEG, -FNEG, -FNEG);
    float ws_acc[16];

    #pragma unroll
    for (int j = 0; j < 16; ++j) {
        float4 v = __ldcs(&xp[(size_t)j * 8 * NPIX4]);
        psum.x += v.x; psum.y += v.y; psum.z += v.z; psum.w += v.w;
        pmax.x = fmaxf(pmax.x, v.x); pmax.y = fmaxf(pmax.y, v.y);
        pmax.z = fmaxf(pmax.z, v.z); pmax.w = fmaxf(pmax.w, v.w);
        float a = v.x * wt.x;
        a = fmaf(v.y, wt.y, a);
        a = fmaf(v.z, wt.z, a);
        a = fmaf(v.w, wt.w, a);
        ws_acc[j] = a;
    }

    ssum[warp][lane] = psum;
    smax[warp][lane] = pmax;
    __syncthreads();

    if (t < 32) {
        float4 a = ssum[0][t];
        #pragma unroll
        for (int w2 = 1; w2 < 8; ++w2) {
            float4 q = ssum[w2][t];
            a.x += q.x; a.y += q.y; a.z += q.z; a.w += q.w;
        }
        const float inv = 1.f / 128.f;
        a.x *= inv; a.y *= inv; a.z *= inv; a.w *= inv;
        ((float4*)g_s)[(size_t)(b*2) * NPIX4 + tile*32 + t] = a;
    } else if (t < 64) {
        int l = t - 32;
        float4 a = smax[0][l];
        #pragma unroll
        for (int w2 = 1; w2 < 8; ++w2) {
            float4 q = smax[w2][l];
            a.x = fmaxf(a.x, q.x); a.y = fmaxf(a.y, q.y);
            a.z = fmaxf(a.z, q.z); a.w = fmaxf(a.w, q.w);
        }
        ((float4*)g_s)[(size_t)(b*2 + 1) * NPIX4 + tile*32 + l] = a;
    }

    // DWT partials: shuffle-reduce each of the 16 channels, one atomic each
    #pragma unroll
    for (int j = 0; j < 16; ++j) {
        float r = warp_sum(ws_acc[j]);
        if (lane == 0) atomicAdd(&g_yraw[b*CC + warp + 8*j], r);
    }
}

// ---------------------------------------------------------------------------
// K23: blocks [0,2048): 7x7 conv + sigmoid -> attn in d_out (8 batches).
//      blocks [2048,2056): FC chain -> w gate.
// ---------------------------------------------------------------------------
__global__ void __launch_bounds__(256) k23_mid(const float* __restrict__ cw,
                                               const float* __restrict__ fc1,
                                               const float* __restrict__ fc2,
                                               float* __restrict__ d_out) {
    int t = threadIdx.x;
    if (blockIdx.x < 2048) {
        // ---- conv ----
        __shared__ float wf[98];
        __shared__ float tile[2][14][40];
        int idx = blockIdx.x & 255;
        int b = blockIdx.x >> 8;
        int tx = t & 31, ty = t >> 5;
        if (t < 98) wf[t] = cw[t];

        int gx0 = (idx & 7) * 32 - 3;
        int gy0 = (idx >> 3) * 8 - 3;
        const float* s0 = g_s + (size_t)b * 2 * NPIX;

        for (int i = t; i < 2*14*38; i += 256) {
            int ic = i / (14*38);
            int r  = (i / 38) % 14;
            int cl = i % 38;
            int gy = gy0 + r, gx = gx0 + cl;
            float v = 0.f;
            if (gy >= 0 && gy < HH && gx >= 0 && gx < WW)
                v = s0[ic*NPIX + gy*WW + gx];
            tile[ic][r][cl] = v;
        }
        __syncthreads();

        float acc = 0.f;
        #pragma unroll
        for (int ic = 0; ic < 2; ++ic)
            #pragma unroll
            for (int ky = 0; ky < 7; ++ky)
                #pragma unroll
                for (int kx = 0; kx < 7; ++kx)
                    acc += tile[ic][ty+ky][tx+kx] * wf[ic*49 + ky*7 + kx];

        int oy = (idx >> 3) * 8 + ty, ox = (idx & 7) * 32 + tx;
        d_out[OFF_ATTN + (size_t)b*NPIX + oy*WW + ox] = 1.f / (1.f + expf(-acc));
    } else {
        // ---- FC ----
        int b = blockIdx.x - 2048;
        __shared__ float y[CC];
        __shared__ float hsm[8];
        if (t < CC) y[t] = g_yraw[b*CC + t] * (1.0f / (135.0f * 135.0f));
        __syncthreads();
        {
            int wj = t >> 5;      // warp 0..7 -> h[wj]
            int lane = t & 31;
            float4 fw = *(const float4*)(fc1 + wj*CC + lane*4);
            float part = fw.x*y[lane*4] + fw.y*y[lane*4+1]
                       + fw.z*y[lane*4+2] + fw.w*y[lane*4+3];
            float hv = warp_sum(part);
            if (lane == 0) hsm[wj] = fmaxf(hv, 0.f);
        }
        __syncthreads();
        if (t < CC) {
            float a = 0.f;
            #pragma unroll
            for (int j = 0; j < 8; ++j) a += fc2[t*8 + j] * hsm[j];
            float wv = 1.f / (1.f + expf(-a));
            g_wch[b*CC + t] = wv;
            d_out[OFF_W + b*CC + t] = wv;
        }
    }
}

// ---------------------------------------------------------------------------
// K4: out = x * (alpha*attn + (1-alpha)*w). 4 float4 per thread, batched
// loads; x last-use streaming, streaming stores. grid 16384, block 256.
// ---------------------------------------------------------------------------
__global__ void __launch_bounds__(256) k4_out(const float* __restrict__ x,
                                              float* __restrict__ d_out) {
    int i0 = blockIdx.x * 1024 + threadIdx.x;
    const float4* x4 = (const float4*)x;
    const float4* a4 = (const float4*)(d_out + OFF_ATTN);
    float alpha = g_alpha;
    float om = 1.f - alpha;

    float4 v[4], at[4];
    float wv[4];
    #pragma unroll
    for (int u = 0; u < 4; ++u) {
        int i = i0 + u * 256;
        v[u] = __ldcs(&x4[i]);
    }
    #pragma unroll
    for (int u = 0; u < 4; ++u) {
        int i = i0 + u * 256;
        int b = i >> 21;
        int g = i & (NPIX4 - 1);
        at[u] = a4[(size_t)b * NPIX4 + g];
        wv[u] = g_wch[i >> 14];
    }
    #pragma unroll
    for (int u = 0; u < 4; ++u) {
        int i = i0 + u * 256;
        float base = om * wv[u];
        float4 o;
        o.x = v[u].x * fmaf(alpha, at[u].x, base);
        o.y = v[u].y * fmaf(alpha, at[u].y, base);
        o.z = v[u].z * fmaf(alpha, at[u].z, base);
        o.w = v[u].w * fmaf(alpha, at[u].w, base);
        __stcs(&((float4*)d_out)[i], o);
    }
}

extern "C" void kernel_launch(void* const* d_in, const int* in_sizes, int n_in,
                              void* d_out, int out_size) {
    const float* x    = (const float*)d_in[0];
    const float* cw   = (const float*)d_in[1];
    const float* fc1  = (const float*)d_in[2];
    const float* fc2  = (const float*)d_in[3];
    const float* wsc  = (const float*)d_in[4];
    float* out = (float*)d_out;

    k0_init<<<1, 288>>>(wsc, out);
    k1_reduce<<<BB * 512, 256>>>(x);
    k23_mid<<<2056, 256>>>(cw, fc1, fc2, out);
    k4_out<<<NOUT/4/1024, 256>>>(x, out);
}

// round 7
// speedup vs baseline: 1.6371x; 1.6371x over previous
#include <cuda_runtime.h>
#include <math.h>

#define BB 8
#define CC 128
#define HH 256
#define WW 256
#define NPIX (HH*WW)        // 65536
#define NPIX4 (NPIX/4)      // 16384
#define NOUT (BB*CC*NPIX)   // 67108864
#define OFF_ATTN ((size_t)NOUT)
#define OFF_W (OFF_ATTN + (size_t)BB*NPIX)
#define OFF_ALPHA (OFF_W + (size_t)BB*CC)
#define FNEG 3.402823466e38f
#define YSPREAD 32           // one accumulator per 128B line

// db8 dec_lo (pywt), fp32
__constant__ float c_declo[16] = {
    -0.00011747678400228192f, 0.0006754494059985568f, -0.0003917403729959771f,
    -0.00487035299301066f, 0.008746094047015655f, 0.013981027917015516f,
    -0.04408825393106472f, -0.01736930100202211f, 0.128747426620186f,
    0.00047248457399797254f, -0.2840155429624281f, -0.015829105256023893f,
    0.5853546836548691f, 0.6756307362980128f, 0.3128715909144659f,
    0.05441584224308161f };

__device__ float g_wa[256];                // per-position separable DWT weight
__device__ float g_ysp[BB*CC*YSPREAD];     // spread DWT accumulators (128KB)
__device__ float g_wch[BB*CC];             // channel gate w
__device__ float g_alpha;
__device__ float g_s[BB*2*NPIX];           // [avg;max] maps, 4 MB scratch

__device__ __forceinline__ float warp_sum(float v) {
    v += __shfl_xor_sync(0xffffffffu, v, 16);
    v += __shfl_xor_sync(0xffffffffu, v, 8);
    v += __shfl_xor_sync(0xffffffffu, v, 4);
    v += __shfl_xor_sync(0xffffffffu, v, 2);
    v += __shfl_xor_sync(0xffffffffu, v, 1);
    return v;
}

// ---------------------------------------------------------------------------
// K0: zero accumulators, build a[256], alpha = sigmoid(weight).
// ---------------------------------------------------------------------------
__global__ void k0_init(const float* __restrict__ weight, float* __restrict__ d_out) {
    int t = threadIdx.x;                      // 288 threads
    if (t < 256) g_wa[t] = 0.f;
    for (int i = t; i < BB*CC; i += 288) g_ysp[i*YSPREAD] = 0.f;
    if (t == 287) {
        float al = 1.f / (1.f + expf(-weight[0]));
        g_alpha = al;
        d_out[OFF_ALPHA] = al;
    }
    __syncthreads();
    if (t < 284) {
        int j = t + 1;                        // 1..284
        int m = (j < 15) ? (14 - j) : ((j <= 270) ? (j - 15) : (526 - j));
        int klo = j - 1 - 268; if (klo < 0) klo = 0;
        int khi = j - 1;       if (khi > 15) khi = 15;
        if ((klo & 1) != ((j - 1) & 1)) klo++;
        float add = 0.f;
        for (int k = klo; k <= khi; k += 2) add += c_declo[15 - k];
        if (add != 0.f) atomicAdd(&g_wa[m], add);
    }
}

// ---------------------------------------------------------------------------
// K1: stats pass. grid 4096 (= BB * 512 tiles), block 256 (8 warps).
// Warp w owns CONSECUTIVE channels 16w..16w+15: its 16 loads stride 256 KB
// and stay inside 2 of the 2MB pages (channel planes 8k..8k+7 share a page)
// -> TLB-friendly, unlike the old w+8j mapping (every load a new page).
// avg/max in regs, combined across warps via 8 KB smem.
// DWT sums: 16 reg accumulators/thread; shuffle-reduce; atomic into
// line-spread g_ysp (one accumulator per 128B line -> hashes across slices).
// ---------------------------------------------------------------------------
__global__ void __launch_bounds__(256) k1_reduce(const float* __restrict__ x) {
    __shared__ float4 ssum[8][32];
    __shared__ float4 smax[8][32];
    int t = threadIdx.x;
    int warp = t >> 5, lane = t & 31;
    int b = blockIdx.x >> 9;                  // batch
    int tile = blockIdx.x & 511;              // 512 tiles of 32 float4
    int g = tile * 32 + lane;                 // float4 index in plane

    float wh = g_wa[g >> 6];
    int w0 = (g & 63) << 2;
    float4 wt = make_float4(g_wa[w0]*wh, g_wa[w0+1]*wh,
                            g_wa[w0+2]*wh, g_wa[w0+3]*wh);

    // warp w -> channels 16w .. 16w+15 (consecutive)
    const float4* xp = (const float4*)x + ((size_t)(b * CC) + warp*16) * NPIX4 + g;

    float4 psum = make_float4(0.f, 0.f, 0.f, 0.f);
    float4 pmax = make_float4(-FNEG, -FNEG, -FNEG, -FNEG);
    float ws_acc[16];

    #pragma unroll
    for (int j = 0; j < 16; ++j) {
        float4 v = __ldcs(&xp[(size_t)j * NPIX4]);
        psum.x += v.x; psum.y += v.y; psum.z += v.z; psum.w += v.w;
        pmax.x = fmaxf(pmax.x, v.x); pmax.y = fmaxf(pmax.y, v.y);
        pmax.z = fmaxf(pmax.z, v.z); pmax.w = fmaxf(pmax.w, v.w);
        float a = v.x * wt.x;
        a = fmaf(v.y, wt.y, a);
        a = fmaf(v.z, wt.z, a);
        a = fmaf(v.w, wt.w, a);
        ws_acc[j] = a;
    }

    ssum[warp][lane] = psum;
    smax[warp][lane] = pmax;
    __syncthreads();

    if (t < 32) {
        float4 a = ssum[0][t];
        #pragma unroll
        for (int w2 = 1; w2 < 8; ++w2) {
            float4 q = ssum[w2][t];
            a.x += q.x; a.y += q.y; a.z += q.z; a.w += q.w;
        }
        const float inv = 1.f / 128.f;
        a.x *= inv; a.y *= inv; a.z *= inv; a.w *= inv;
        ((float4*)g_s)[(size_t)(b*2) * NPIX4 + tile*32 + t] = a;
    } else if (t < 64) {
        int l = t - 32;
        float4 a = smax[0][l];
        #pragma unroll
        for (int w2 = 1; w2 < 8; ++w2) {
            float4 q = smax[w2][l];
            a.x = fmaxf(a.x, q.x); a.y = fmaxf(a.y, q.y);
            a.z = fmaxf(a.z, q.z); a.w = fmaxf(a.w, q.w);
        }
        ((float4*)g_s)[(size_t)(b*2 + 1) * NPIX4 + tile*32 + l] = a;
    }

    // DWT partials: shuffle-reduce each channel, one line-spread atomic each
    #pragma unroll
    for (int j = 0; j < 16; ++j) {
        float r = warp_sum(ws_acc[j]);
        if (lane == 0) atomicAdd(&g_ysp[(b*CC + warp*16 + j) * YSPREAD], r);
    }
}

// ---------------------------------------------------------------------------
// K23: blocks [0,2048): 7x7 conv + sigmoid -> attn in d_out (8 batches).
//      blocks [2048,2056): FC chain -> w gate.
// ---------------------------------------------------------------------------
__global__ void __launch_bounds__(256) k23_mid(const float* __restrict__ cw,
                                               const float* __restrict__ fc1,
                                               const float* __restrict__ fc2,
                                               float* __restrict__ d_out) {
    int t = threadIdx.x;
    if (blockIdx.x < 2048) {
        // ---- conv ----
        __shared__ float wf[98];
        __shared__ float tile[2][14][40];
        int idx = blockIdx.x & 255;
        int b = blockIdx.x >> 8;
        int tx = t & 31, ty = t >> 5;
        if (t < 98) wf[t] = cw[t];

        int gx0 = (idx & 7) * 32 - 3;
        int gy0 = (idx >> 3) * 8 - 3;
        const float* s0 = g_s + (size_t)b * 2 * NPIX;

        for (int i = t; i < 2*14*38; i += 256) {
            int ic = i / (14*38);
            int r  = (i / 38) % 14;
            int cl = i % 38;
            int gy = gy0 + r, gx = gx0 + cl;
            float v = 0.f;
            if (gy >= 0 && gy < HH && gx >= 0 && gx < WW)
                v = s0[ic*NPIX + gy*WW + gx];
            tile[ic][r][cl] = v;
        }
        __syncthreads();

        float acc = 0.f;
        #pragma unroll
        for (int ic = 0; ic < 2; ++ic)
            #pragma unroll
            for (int ky = 0; ky < 7; ++ky)
                #pragma unroll
                for (int kx = 0; kx < 7; ++kx)
                    acc += tile[ic][ty+ky][tx+kx] * wf[ic*49 + ky*7 + kx];

        int oy = (idx >> 3) * 8 + ty, ox = (idx & 7) * 32 + tx;
        d_out[OFF_ATTN + (size_t)b*NPIX + oy*WW + ox] = 1.f / (1.f + expf(-acc));
    } else {
        // ---- FC ----
        int b = blockIdx.x - 2048;
        __shared__ float y[CC];
        __shared__ float hsm[8];
        if (t < CC) y[t] = g_ysp[(b*CC + t) * YSPREAD] * (1.0f / (135.0f * 135.0f));
        __syncthreads();
        {
            int wj = t >> 5;      // warp 0..7 -> h[wj]
            int lane = t & 31;
            float4 fw = *(const float4*)(fc1 + wj*CC + lane*4);
            float part = fw.x*y[lane*4] + fw.y*y[lane*4+1]
                       + fw.z*y[lane*4+2] + fw.w*y[lane*4+3];
            float hv = warp_sum(part);
            if (lane == 0) hsm[wj] = fmaxf(hv, 0.f);
        }
        __syncthreads();
        if (t < CC) {
            float a = 0.f;
            #pragma unroll
            for (int j = 0; j < 8; ++j) a += fc2[t*8 + j] * hsm[j];
            float wv = 1.f / (1.f + expf(-a));
            g_wch[b*CC + t] = wv;
            d_out[OFF_W + b*CC + t] = wv;
        }
    }
}

// ---------------------------------------------------------------------------
// K4: out = x * (alpha*attn + (1-alpha)*w). 4 float4 per thread, batched
// loads; x last-use streaming, streaming stores. grid 16384, block 256.
// ---------------------------------------------------------------------------
__global__ void __launch_bounds__(256) k4_out(const float* __restrict__ x,
                                              float* __restrict__ d_out) {
    int i0 = blockIdx.x * 1024 + threadIdx.x;
    const float4* x4 = (const float4*)x;
    const float4* a4 = (const float4*)(d_out + OFF_ATTN);
    float alpha = g_alpha;
    float om = 1.f - alpha;

    float4 v[4], at[4];
    float wv[4];
    #pragma unroll
    for (int u = 0; u < 4; ++u) {
        int i = i0 + u * 256;
        v[u] = __ldcs(&x4[i]);
    }
    #pragma unroll
    for (int u = 0; u < 4; ++u) {
        int i = i0 + u * 256;
        int b = i >> 21;
        int g = i & (NPIX4 - 1);
        at[u] = a4[(size_t)b * NPIX4 + g];
        wv[u] = g_wch[i >> 14];
    }
    #pragma unroll
    for (int u = 0; u < 4; ++u) {
        int i = i0 + u * 256;
        float base = om * wv[u];
        float4 o;
        o.x = v[u].x * fmaf(alpha, at[u].x, base);
        o.y = v[u].y * fmaf(alpha, at[u].y, base);
        o.z = v[u].z * fmaf(alpha, at[u].z, base);
        o.w = v[u].w * fmaf(alpha, at[u].w, base);
        __stcs(&((float4*)d_out)[i], o);
    }
}

extern "C" void kernel_launch(void* const* d_in, const int* in_sizes, int n_in,
                              void* d_out, int out_size) {
    const float* x    = (const float*)d_in[0];
    const float* cw   = (const float*)d_in[1];
    const float* fc1  = (const float*)d_in[2];
    const float* fc2  = (const float*)d_in[3];
    const float* wsc  = (const float*)d_in[4];
    float* out = (float*)d_out;

    k0_init<<<1, 288>>>(wsc, out);
    k1_reduce<<<BB * 512, 256>>>(x);
    k23_mid<<<2056, 256>>>(cw, fc1, fc2, out);
    k4_out<<<NOUT/4/1024, 256>>>(x, out);
}